// round 12
// baseline (speedup 1.0000x reference)
#include <cuda_runtime.h>

#define B_   256
#define IN_  256
#define OUT_ 512
#define EPS_ 1e-7f

__device__ float g_relx[IN_ * OUT_];               // rel_x[i][o]
__device__ unsigned long long g_key[4 * 128 * 1024]; // partial argmax keys
__device__ int g_cnt[128];                          // rendezvous counters (never reset)

// ---------------------------------------------------------------------------
// Kernel 1: rel_x[i,o] = (sum_b min(t[b,o]/(x[b,i]+eps),1)) / colsum[i]
// (unchanged from R10 — measured stable)
// ---------------------------------------------------------------------------
__global__ void k_relx(const float* __restrict__ x, const float* __restrict__ t) {
    __shared__ float Rs[128][32];
    __shared__ float Ts[128][16];
    __shared__ float ps[8][32];
    __shared__ float s_cs[32];

    const int i0  = blockIdx.x * 32;
    const int o0  = blockIdx.y * 16;
    const int lid = threadIdx.x;
    const int to  = lid & 15;
    const int tp  = lid >> 4;

    {
        const int il  = lid & 31;
        const int seg = lid >> 5;
        float s = 0.0f;
        #pragma unroll
        for (int j = 0; j < 32; j++)
            s += x[(seg * 32 + j) * IN_ + i0 + il];
        ps[seg][il] = s;
    }

    float acc0 = 0.f, acc1 = 0.f;

    for (int bb = 0; bb < B_; bb += 128) {
        #pragma unroll
        for (int k = 0; k < 4; k++) {
            int e   = lid + k * 256;
            int row = e >> 3;
            int c4  = (e & 7) * 4;
            float4 xv = *(const float4*)&x[(bb + row) * IN_ + i0 + c4];
            float4 rv;
            rv.x = 1.0f / (xv.x + EPS_);
            rv.y = 1.0f / (xv.y + EPS_);
            rv.z = 1.0f / (xv.z + EPS_);
            rv.w = 1.0f / (xv.w + EPS_);
            *(float4*)&Rs[row][c4] = rv;
        }
        #pragma unroll
        for (int k = 0; k < 2; k++) {
            int e   = lid + k * 256;
            int row = e >> 2;
            int c4  = (e & 3) * 4;
            *(float4*)&Ts[row][c4] = *(const float4*)&t[(bb + row) * OUT_ + o0 + c4];
        }
        __syncthreads();

        if (bb == 0 && lid < 32) {
            float s = ps[0][lid];
            #pragma unroll
            for (int c = 1; c < 8; c++) s += ps[c][lid];
            s_cs[lid] = s;
        }

        #pragma unroll 8
        for (int b = 0; b < 128; b++) {
            float2 r  = *(const float2*)&Rs[b][2 * tp];
            float  tv = Ts[b][to];
            acc0 += fminf(tv * r.x, 1.0f);
            acc1 += fminf(tv * r.y, 1.0f);
        }
        __syncthreads();
    }

    const int i_0 = i0 + 2 * tp, i_1 = i_0 + 1;
    const int o   = o0 + to;
    g_relx[i_0 * OUT_ + o] = acc0 / s_cs[2 * tp];
    g_relx[i_1 * OUT_ + o] = acc1 / s_cs[2 * tp + 1];
}

// ---------------------------------------------------------------------------
// Kernel 2: 4-way i-split argmax. Grid (8,16,4)=512 blocks, 256 thr.
// Tile 32b x 32o; block z covers i in [z*64, z*64+64); thread 2b x 2o.
// Partial keys (valbits<<32 | ~id, exact first-max) -> global; 4th arriver
// per tile (threadfence + counter parity) combines, runs w-argmax, gathers,
// writes outx/outw.
// ---------------------------------------------------------------------------
__global__ void k_argmax(const float* __restrict__ x,
                         const float* __restrict__ w,
                         float* __restrict__ outx,
                         float* __restrict__ outw) {
    __shared__ float Xs[64][34];    // [i_local][b_local] transposed, padded
    __shared__ float Rl[64][32];    // [i_local][o_local]
    __shared__ float sv[8][32];
    __shared__ int   si[8][32];
    __shared__ float s_wv[32];
    __shared__ int   s_iw[32];
    __shared__ int   s_flag;

    const int b0   = blockIdx.x * 32;
    const int o0   = blockIdx.y * 32;
    const int z    = blockIdx.z;
    const int iz   = z * 64;
    const int tile = blockIdx.y * 8 + blockIdx.x;   // 0..127
    const int lid  = threadIdx.x;
    const int tb   = lid & 15;    // b pair: 2tb, 2tb+1
    const int to   = lid >> 4;    // o pair: 2to, 2to+1

    // --- stage Xs (transposed) and Rl for this 64-i slice ---
    #pragma unroll
    for (int k = 0; k < 2; k++) {
        int e   = lid + k * 256;        // 0..511
        int row = e >> 4;               // b-local 0..31
        int c4  = (e & 15) * 4;         // i-local 0..60
        float4 v = *(const float4*)&x[(b0 + row) * IN_ + iz + c4];
        Xs[c4 + 0][row] = v.x;
        Xs[c4 + 1][row] = v.y;
        Xs[c4 + 2][row] = v.z;
        Xs[c4 + 3][row] = v.w;
    }
    #pragma unroll
    for (int k = 0; k < 2; k++) {
        int e   = lid + k * 256;
        int row = e >> 3;               // i-local 0..63
        int c4  = (e & 7) * 4;
        *(float4*)&Rl[row][c4] = *(const float4*)&g_relx[(iz + row) * OUT_ + o0 + c4];
    }
    __syncthreads();

    // --- partial argmax over 64 i (select tracking, strict >, exact) ---
    float best00 = -1.f, best01 = -1.f, best10 = -1.f, best11 = -1.f;
    int   id00 = iz, id01 = iz, id10 = iz, id11 = iz;

    #pragma unroll 8
    for (int i = 0; i < 64; i++) {
        const int gi = iz + i;
        float2 xv = *(const float2*)&Xs[i][2 * tb];
        float2 rv = *(const float2*)&Rl[i][2 * to];
        float v;
        v = xv.x * rv.x; if (v > best00) { best00 = v; id00 = gi; }
        v = xv.x * rv.y; if (v > best01) { best01 = v; id01 = gi; }
        v = xv.y * rv.x; if (v > best10) { best10 = v; id10 = gi; }
        v = xv.y * rv.y; if (v > best11) { best11 = v; id11 = gi; }
    }

    // --- publish partial keys (coalesced) ---
    const unsigned long long kb = (unsigned long long)(z * 128 + tile) * 1024ull;
    g_key[kb + 0 * 256 + lid] = ((unsigned long long)__float_as_uint(best00) << 32) | (unsigned)(~id00);
    g_key[kb + 1 * 256 + lid] = ((unsigned long long)__float_as_uint(best01) << 32) | (unsigned)(~id01);
    g_key[kb + 2 * 256 + lid] = ((unsigned long long)__float_as_uint(best10) << 32) | (unsigned)(~id10);
    g_key[kb + 3 * 256 + lid] = ((unsigned long long)__float_as_uint(best11) << 32) | (unsigned)(~id11);
    __threadfence();

    if (lid == 0) {
        int old = atomicAdd(&g_cnt[tile], 1);
        s_flag = ((old & 3) == 3);
    }
    __syncthreads();
    if (!s_flag) return;          // uniform block exit
    __threadfence();

    // ===================== winner block epilogue =====================

    // --- combine 4 partial key sets (read all, incl. own: simplest) ---
    unsigned long long k00 = 0, k01 = 0, k10 = 0, k11 = 0;
    #pragma unroll
    for (int zp = 0; zp < 4; zp++) {
        const unsigned long long pb = (unsigned long long)(zp * 128 + tile) * 1024ull;
        unsigned long long a = g_key[pb + 0 * 256 + lid];
        unsigned long long b = g_key[pb + 1 * 256 + lid];
        unsigned long long c = g_key[pb + 2 * 256 + lid];
        unsigned long long d = g_key[pb + 3 * 256 + lid];
        if (a > k00) k00 = a;
        if (b > k01) k01 = b;
        if (c > k10) k10 = c;
        if (d > k11) k11 = d;
    }
    const int f00 = (int)(~(unsigned)k00);
    const int f01 = (int)(~(unsigned)k01);
    const int f10 = (int)(~(unsigned)k10);
    const int f11 = (int)(~(unsigned)k11);

    // --- w-argmax for this tile's 32 o's: thread (ic, ol) scans 32 i's ---
    {
        const int ol = lid & 31;
        const int ic = lid >> 5;
        const int o  = o0 + ol;
        float best = -1.f;
        int   bi   = 0;
        #pragma unroll
        for (int j = 0; j < 32; j++) {
            int i = ic * 32 + j;
            float v = w[i * OUT_ + o];
            if (v > best) { best = v; bi = i; }
        }
        sv[ic][ol] = best;
        si[ic][ol] = bi;
    }
    __syncthreads();
    if (lid < 32) {
        float bv = sv[0][lid];
        int   ix = si[0][lid];
        #pragma unroll
        for (int c = 1; c < 8; c++)
            if (sv[c][lid] > bv) { bv = sv[c][lid]; ix = si[c][lid]; }
        s_wv[lid] = bv;
        s_iw[lid] = ix;
    }
    __syncthreads();

    // --- outputs ---
    const int b_0 = b0 + 2 * tb, b_1 = b_0 + 1;
    const int o_0 = o0 + 2 * to;

    float2 ox0, ox1;
    ox0.x = x[b_0 * IN_ + f00] * w[f00 * OUT_ + o_0];
    ox0.y = x[b_0 * IN_ + f01] * w[f01 * OUT_ + o_0 + 1];
    ox1.x = x[b_1 * IN_ + f10] * w[f10 * OUT_ + o_0];
    ox1.y = x[b_1 * IN_ + f11] * w[f11 * OUT_ + o_0 + 1];
    *(float2*)&outx[b_0 * OUT_ + o_0] = ox0;
    *(float2*)&outx[b_1 * OUT_ + o_0] = ox1;

    const int lo0 = 2 * to, lo1 = 2 * to + 1;
    const int iw0 = s_iw[lo0], iw1 = s_iw[lo1];
    const float wv0 = s_wv[lo0], wv1 = s_wv[lo1];
    float2 ow0, ow1;
    ow0.x = x[b_0 * IN_ + iw0] * wv0;
    ow0.y = x[b_0 * IN_ + iw1] * wv1;
    ow1.x = x[b_1 * IN_ + iw0] * wv0;
    ow1.y = x[b_1 * IN_ + iw1] * wv1;
    *(float2*)&outw[b_0 * OUT_ + o_0] = ow0;
    *(float2*)&outw[b_1 * OUT_ + o_0] = ow1;
}

// ---------------------------------------------------------------------------
extern "C" void kernel_launch(void* const* d_in, const int* in_sizes, int n_in,
                              void* d_out, int out_size) {
    const float* x = (const float*)d_in[0];
    const float* w = (const float*)d_in[1];
    const float* t = (const float*)d_in[2];
    float* outx = (float*)d_out;
    float* outw = (float*)d_out + B_ * OUT_;

    k_relx  <<<dim3(IN_ / 32, OUT_ / 16), 256>>>(x, t);
    k_argmax<<<dim3(B_  / 32, OUT_ / 32, 4), 256>>>(x, w, outx, outw);
}

// round 13
// speedup vs baseline: 1.0600x; 1.0600x over previous
#include <cuda_runtime.h>

#define B_   256
#define IN_  256
#define OUT_ 512
#define EPS_ 1e-7f

__device__ float g_relx[IN_ * OUT_];                // rel_x[i][o]
__device__ int   g_iw[OUT_];                        // argmax_i w[i,o]
__device__ float g_wv[OUT_];                        // w[iw,o]
__device__ unsigned long long g_key[256 * 1024];    // packed argmax partials
__device__ int   g_cnt[256];                        // parity rendezvous (never reset)

// ---------------------------------------------------------------------------
// Kernel 1: grid (8,34).
//  by<32 : rel_x tiles (R10 verbatim): 32i x 16o, 2i x 1o/thread.
//  by>=32: w-argmax role, 16 blocks, each 32 o's (8 i-chunks x 32 lanes,
//          exact first-max merge) -> g_iw/g_wv.
// ---------------------------------------------------------------------------
__global__ void k_relx(const float* __restrict__ x, const float* __restrict__ t,
                       const float* __restrict__ w) {
    __shared__ float Rs[128][32];
    __shared__ float Ts[128][16];
    __shared__ float ps[8][32];
    __shared__ float s_cs[32];

    if (blockIdx.y >= 32) {
        // ---- w-argmax role ----
        __shared__ float sv[8][32];
        __shared__ int   si[8][32];
        const int wb  = (blockIdx.y - 32) * 8 + blockIdx.x;   // 0..15
        const int lid = threadIdx.x;
        const int ol  = lid & 31;
        const int ic  = lid >> 5;
        const int o   = wb * 32 + ol;
        float best = -1.f;
        int   bi   = 0;
        #pragma unroll
        for (int j = 0; j < 32; j++) {
            int i = ic * 32 + j;
            float v = w[i * OUT_ + o];
            if (v > best) { best = v; bi = i; }
        }
        sv[ic][ol] = best;
        si[ic][ol] = bi;
        __syncthreads();
        if (lid < 32) {
            float bv = sv[0][lid];
            int   ix = si[0][lid];
            #pragma unroll
            for (int c = 1; c < 8; c++)
                if (sv[c][lid] > bv) { bv = sv[c][lid]; ix = si[c][lid]; }
            g_wv[wb * 32 + lid] = bv;
            g_iw[wb * 32 + lid] = ix;
        }
        return;
    }

    // ---- rel_x role (R10 verbatim) ----
    const int i0  = blockIdx.x * 32;
    const int o0  = blockIdx.y * 16;
    const int lid = threadIdx.x;
    const int to  = lid & 15;
    const int tp  = lid >> 4;

    {
        const int il  = lid & 31;
        const int seg = lid >> 5;
        float s = 0.0f;
        #pragma unroll
        for (int j = 0; j < 32; j++)
            s += x[(seg * 32 + j) * IN_ + i0 + il];
        ps[seg][il] = s;
    }

    float acc0 = 0.f, acc1 = 0.f;

    for (int bb = 0; bb < B_; bb += 128) {
        #pragma unroll
        for (int k = 0; k < 4; k++) {
            int e   = lid + k * 256;
            int row = e >> 3;
            int c4  = (e & 7) * 4;
            float4 xv = *(const float4*)&x[(bb + row) * IN_ + i0 + c4];
            float4 rv;
            rv.x = 1.0f / (xv.x + EPS_);
            rv.y = 1.0f / (xv.y + EPS_);
            rv.z = 1.0f / (xv.z + EPS_);
            rv.w = 1.0f / (xv.w + EPS_);
            *(float4*)&Rs[row][c4] = rv;
        }
        #pragma unroll
        for (int k = 0; k < 2; k++) {
            int e   = lid + k * 256;
            int row = e >> 2;
            int c4  = (e & 3) * 4;
            *(float4*)&Ts[row][c4] = *(const float4*)&t[(bb + row) * OUT_ + o0 + c4];
        }
        __syncthreads();

        if (bb == 0 && lid < 32) {
            float s = ps[0][lid];
            #pragma unroll
            for (int c = 1; c < 8; c++) s += ps[c][lid];
            s_cs[lid] = s;
        }

        #pragma unroll 8
        for (int b = 0; b < 128; b++) {
            float2 r  = *(const float2*)&Rs[b][2 * tp];
            float  tv = Ts[b][to];
            acc0 += fminf(tv * r.x, 1.0f);
            acc1 += fminf(tv * r.y, 1.0f);
        }
        __syncthreads();
    }

    const int i_0 = i0 + 2 * tp, i_1 = i_0 + 1;
    const int o   = o0 + to;
    g_relx[i_0 * OUT_ + o] = acc0 / s_cs[2 * tp];
    g_relx[i_1 * OUT_ + o] = acc1 / s_cs[2 * tp + 1];
}

// ---------------------------------------------------------------------------
// Kernel 2: argmax, grid (16,16,2) = 512 blocks, 256 thr.
// Tile 16b x 32o, 1b x 2o/thread (R10 loop), z covers i in [z*128, z*128+128).
// fmax-only inner + chunk-of-32 tracking + in-smem rescan (exact first-max).
// Packed keys -> g_key; second arriver per tile (parity atomic, replay-safe)
// combines both slices, gathers outx, writes outw from g_iw/g_wv.
// ---------------------------------------------------------------------------
__global__ void k_argmax(const float* __restrict__ x,
                         const float* __restrict__ w,
                         float* __restrict__ outx,
                         float* __restrict__ outw) {
    __shared__ float Xs[16][132];   // [b_local][i_local]
    __shared__ float Rl[128][32];   // [i_local][o_local]
    __shared__ int   s_flag;

    const int b0   = blockIdx.x * 16;
    const int o0   = blockIdx.y * 32;
    const int z    = blockIdx.z;
    const int iz   = z * 128;
    const int tile = blockIdx.y * 16 + blockIdx.x;  // 0..255
    const int lid  = threadIdx.x;
    const int to   = lid & 15;   // o pair: 2to, 2to+1
    const int tb   = lid >> 4;   // b: 0..15

    // --- stage Xs and Rl for this slice (R10 verbatim staging) ---
    #pragma unroll
    for (int k = 0; k < 2; k++) {
        int e   = lid + k * 256;
        int row = e >> 5;               // b-local 0..15
        int c4  = (e & 31) * 4;         // i-local
        *(float4*)&Xs[row][c4] = *(const float4*)&x[(b0 + row) * IN_ + iz + c4];
    }
    #pragma unroll
    for (int k = 0; k < 4; k++) {
        int e   = lid + k * 256;
        int row = e >> 3;
        int c4  = (e & 7) * 4;
        *(float4*)&Rl[row][c4] = *(const float4*)&g_relx[(iz + row) * OUT_ + o0 + c4];
    }
    __syncthreads();

    // --- fmax-only main loop with chunk tracking (R10 loop body) ---
    float best0 = -1.f, best1 = -1.f;
    int   bc0 = 0, bc1 = 0;

    #pragma unroll
    for (int c = 0; c < 4; c++) {
        float cm0 = -1.f, cm1 = -1.f;
        #pragma unroll
        for (int j = 0; j < 32; j++) {
            int i = c * 32 + j;
            float  xv = Xs[tb][i];
            float2 rv = *(const float2*)&Rl[i][2 * to];
            cm0 = fmaxf(cm0, xv * rv.x);
            cm1 = fmaxf(cm1, xv * rv.y);
        }
        if (cm0 > best0) { best0 = cm0; bc0 = c * 32; }
        if (cm1 > best1) { best1 = cm1; bc1 = c * 32; }
    }

    // --- in-smem rescans (descending j, == overwrite -> exact first index) ---
    int id0 = iz + bc0, id1 = iz + bc1;
    #pragma unroll 8
    for (int j = 31; j >= 0; j--)
        if (Xs[tb][bc0 + j] * Rl[bc0 + j][2 * to] == best0) id0 = iz + bc0 + j;
    #pragma unroll 8
    for (int j = 31; j >= 0; j--)
        if (Xs[tb][bc1 + j] * Rl[bc1 + j][2 * to + 1] == best1) id1 = iz + bc1 + j;

    // --- publish packed keys (coalesced) ---
    const int kb = tile * 1024 + z * 512;
    g_key[kb + lid]       = ((unsigned long long)__float_as_uint(best0) << 32) | (unsigned)(~id0);
    g_key[kb + 256 + lid] = ((unsigned long long)__float_as_uint(best1) << 32) | (unsigned)(~id1);
    __threadfence();

    if (lid == 0) {
        int old = atomicAdd(&g_cnt[tile], 1);
        s_flag = (old & 1);            // second arriver wins (replay-safe parity)
    }
    __syncthreads();
    if (!s_flag) return;
    __threadfence();

    // --- winner epilogue: combine both slices, gather, write outputs ---
    unsigned long long ka0 = g_key[tile * 1024 + lid];
    unsigned long long kb0 = g_key[tile * 1024 + 512 + lid];
    unsigned long long ka1 = g_key[tile * 1024 + 256 + lid];
    unsigned long long kb1 = g_key[tile * 1024 + 768 + lid];
    const int f0 = (int)(~(unsigned)((ka0 >= kb0) ? ka0 : kb0));
    const int f1 = (int)(~(unsigned)((ka1 >= kb1) ? ka1 : kb1));

    const int b  = b0 + tb;
    const int o_ = o0 + 2 * to;

    float2 ox;
    ox.x = x[b * IN_ + f0] * w[f0 * OUT_ + o_];
    ox.y = x[b * IN_ + f1] * w[f1 * OUT_ + o_ + 1];
    *(float2*)&outx[b * OUT_ + o_] = ox;

    const int iw0 = g_iw[o_], iw1 = g_iw[o_ + 1];
    float2 ow;
    ow.x = x[b * IN_ + iw0] * g_wv[o_];
    ow.y = x[b * IN_ + iw1] * g_wv[o_ + 1];
    *(float2*)&outw[b * OUT_ + o_] = ow;
}

// ---------------------------------------------------------------------------
extern "C" void kernel_launch(void* const* d_in, const int* in_sizes, int n_in,
                              void* d_out, int out_size) {
    const float* x = (const float*)d_in[0];
    const float* w = (const float*)d_in[1];
    const float* t = (const float*)d_in[2];
    float* outx = (float*)d_out;
    float* outw = (float*)d_out + B_ * OUT_;

    k_relx  <<<dim3(8, 34),     256>>>(x, t, w);
    k_argmax<<<dim3(16, 16, 2), 256>>>(x, w, outx, outw);
}

// round 14
// speedup vs baseline: 1.0850x; 1.0236x over previous
#include <cuda_runtime.h>

#define B_   256
#define IN_  256
#define OUT_ 512
#define EPS_ 1e-7f

__device__ float g_relx[IN_ * OUT_];   // rel_x[i][o]
__device__ int   g_iw[OUT_];           // argmax_i w[i,o]
__device__ float g_wv[OUT_];           // w[iw,o]

// ---------------------------------------------------------------------------
// Kernel 1: grid (8,34).
//  by<32 : rel_x tiles: 32i x 16o, 2i x 1o/thread (R10 loop, proven).
//  by>=32: w-argmax role, 16 blocks, each 32 o's (8 i-chunks x 32 lanes,
//          exact first-max merge) -> g_iw/g_wv.   (R13 structure, proven)
// ---------------------------------------------------------------------------
__global__ void k_relx(const float* __restrict__ x, const float* __restrict__ t,
                       const float* __restrict__ w) {
    __shared__ float Rs[128][32];
    __shared__ float Ts[128][16];
    __shared__ float ps[8][32];
    __shared__ float s_cs[32];

    if (blockIdx.y >= 32) {
        // ---- w-argmax role ----
        __shared__ float sv[8][32];
        __shared__ int   si[8][32];
        const int wb  = (blockIdx.y - 32) * 8 + blockIdx.x;   // 0..15
        const int lid = threadIdx.x;
        const int ol  = lid & 31;
        const int ic  = lid >> 5;
        const int o   = wb * 32 + ol;
        float best = -1.f;
        int   bi   = 0;
        #pragma unroll
        for (int j = 0; j < 32; j++) {
            int i = ic * 32 + j;
            float v = w[i * OUT_ + o];
            if (v > best) { best = v; bi = i; }
        }
        sv[ic][ol] = best;
        si[ic][ol] = bi;
        __syncthreads();
        if (lid < 32) {
            float bv = sv[0][lid];
            int   ix = si[0][lid];
            #pragma unroll
            for (int c = 1; c < 8; c++)
                if (sv[c][lid] > bv) { bv = sv[c][lid]; ix = si[c][lid]; }
            g_wv[wb * 32 + lid] = bv;
            g_iw[wb * 32 + lid] = ix;
        }
        return;
    }

    // ---- rel_x role ----
    const int i0  = blockIdx.x * 32;
    const int o0  = blockIdx.y * 16;
    const int lid = threadIdx.x;
    const int to  = lid & 15;
    const int tp  = lid >> 4;

    {
        const int il  = lid & 31;
        const int seg = lid >> 5;
        float s = 0.0f;
        #pragma unroll
        for (int j = 0; j < 32; j++)
            s += x[(seg * 32 + j) * IN_ + i0 + il];
        ps[seg][il] = s;
    }

    float acc0 = 0.f, acc1 = 0.f;

    for (int bb = 0; bb < B_; bb += 128) {
        #pragma unroll
        for (int k = 0; k < 4; k++) {
            int e   = lid + k * 256;
            int row = e >> 3;
            int c4  = (e & 7) * 4;
            float4 xv = *(const float4*)&x[(bb + row) * IN_ + i0 + c4];
            float4 rv;
            rv.x = 1.0f / (xv.x + EPS_);
            rv.y = 1.0f / (xv.y + EPS_);
            rv.z = 1.0f / (xv.z + EPS_);
            rv.w = 1.0f / (xv.w + EPS_);
            *(float4*)&Rs[row][c4] = rv;
        }
        #pragma unroll
        for (int k = 0; k < 2; k++) {
            int e   = lid + k * 256;
            int row = e >> 2;
            int c4  = (e & 3) * 4;
            *(float4*)&Ts[row][c4] = *(const float4*)&t[(bb + row) * OUT_ + o0 + c4];
        }
        __syncthreads();

        if (bb == 0 && lid < 32) {
            float s = ps[0][lid];
            #pragma unroll
            for (int c = 1; c < 8; c++) s += ps[c][lid];
            s_cs[lid] = s;
        }

        #pragma unroll 8
        for (int b = 0; b < 128; b++) {
            float2 r  = *(const float2*)&Rs[b][2 * tp];
            float  tv = Ts[b][to];
            acc0 += fminf(tv * r.x, 1.0f);
            acc1 += fminf(tv * r.y, 1.0f);
        }
        __syncthreads();
    }

    const int i_0 = i0 + 2 * tp, i_1 = i_0 + 1;
    const int o   = o0 + to;
    g_relx[i_0 * OUT_ + o] = acc0 / s_cs[2 * tp];
    g_relx[i_1 * OUT_ + o] = acc1 / s_cs[2 * tp + 1];
}

// ---------------------------------------------------------------------------
// Kernel 2: argmax_i x[b,i]*relx[i,o] — R10 kernel verbatim, minus the
// w-argmax prologue (now read from g_iw/g_wv). fmax-only inner loop,
// chunk-of-32 tracking, in-smem rescan (exact first-max), direct outputs.
// Tile 16b x 32o, 256 thr (o fastest), 1b x 2o/thread. Grid (16,16)=256.
// ---------------------------------------------------------------------------
__global__ void k_argmax(const float* __restrict__ x,
                         const float* __restrict__ w,
                         float* __restrict__ outx,
                         float* __restrict__ outw) {
    __shared__ float Xs[16][132];   // [b_local][i] half-tile (128 i + pad)
    __shared__ float Rl[128][32];   // [i][o_local]

    const int b0  = blockIdx.x * 16;
    const int o0  = blockIdx.y * 32;
    const int lid = threadIdx.x;
    const int to  = lid & 15;    // o pair: 2to, 2to+1
    const int tb  = lid >> 4;    // b: 0..15

    float best0 = -1.f, best1 = -1.f;
    int   bc0 = 0, bc1 = 0;
    int   id0 = 0, id1 = 0;

    for (int half = 0; half < 2; half++) {
        const int iz = half * 128;
        #pragma unroll
        for (int k = 0; k < 2; k++) {       // Xs: [16 b][128 i], float4 rows
            int e   = lid + k * 256;        // 0..511
            int row = e >> 5;               // b-local 0..15
            int c4  = (e & 31) * 4;         // i-local 0..124
            *(float4*)&Xs[row][c4] = *(const float4*)&x[(b0 + row) * IN_ + iz + c4];
        }
        #pragma unroll
        for (int k = 0; k < 4; k++) {       // Rl: [128 i][32 o]
            int e   = lid + k * 256;
            int row = e >> 3;
            int c4  = (e & 7) * 4;
            *(float4*)&Rl[row][c4] = *(const float4*)&g_relx[(iz + row) * OUT_ + o0 + c4];
        }
        __syncthreads();

        #pragma unroll
        for (int c = 0; c < 4; c++) {
            float cm0 = -1.f, cm1 = -1.f;
            #pragma unroll
            for (int j = 0; j < 32; j++) {
                int i = c * 32 + j;
                float  xv = Xs[tb][i];
                float2 rv = *(const float2*)&Rl[i][2 * to];
                cm0 = fmaxf(cm0, xv * rv.x);
                cm1 = fmaxf(cm1, xv * rv.y);
            }
            const int cb = iz + c * 32;
            if (cm0 > best0) { best0 = cm0; bc0 = cb; }
            if (cm1 > best1) { best1 = cm1; bc1 = cb; }
        }

        // In-smem rescans (descending j, == overwrite -> exact first index)
        if (bc0 >= iz) {
            const int cl = bc0 - iz;
            #pragma unroll 8
            for (int j = 31; j >= 0; j--)
                if (Xs[tb][cl + j] * Rl[cl + j][2 * to] == best0) id0 = bc0 + j;
        }
        if (bc1 >= iz) {
            const int cl = bc1 - iz;
            #pragma unroll 8
            for (int j = 31; j >= 0; j--)
                if (Xs[tb][cl + j] * Rl[cl + j][2 * to + 1] == best1) id1 = bc1 + j;
        }
        __syncthreads();
    }

    const int b  = b0 + tb;
    const int o_ = o0 + 2 * to;

    float2 ox;
    ox.x = x[b * IN_ + id0] * w[id0 * OUT_ + o_];
    ox.y = x[b * IN_ + id1] * w[id1 * OUT_ + o_ + 1];
    *(float2*)&outx[b * OUT_ + o_] = ox;

    const int iw0 = g_iw[o_], iw1 = g_iw[o_ + 1];
    float2 ow;
    ow.x = x[b * IN_ + iw0] * g_wv[o_];
    ow.y = x[b * IN_ + iw1] * g_wv[o_ + 1];
    *(float2*)&outw[b * OUT_ + o_] = ow;
}

// ---------------------------------------------------------------------------
extern "C" void kernel_launch(void* const* d_in, const int* in_sizes, int n_in,
                              void* d_out, int out_size) {
    const float* x = (const float*)d_in[0];
    const float* w = (const float*)d_in[1];
    const float* t = (const float*)d_in[2];
    float* outx = (float*)d_out;
    float* outw = (float*)d_out + B_ * OUT_;

    k_relx  <<<dim3(8, 34),   256>>>(x, t, w);
    k_argmax<<<dim3(16, 16),  256>>>(x, w, outx, outw);
}

// round 15
// speedup vs baseline: 1.1722x; 1.0804x over previous
#include <cuda_runtime.h>

#define B_   256
#define IN_  256
#define OUT_ 512
#define EPS_ 1e-7f

__device__ float g_relx[IN_ * OUT_];   // rel_x[i][o]

// ---------------------------------------------------------------------------
// Kernel 1: rel_x[i,o] = (sum_b min(t[b,o]/(x[b,i]+eps),1)) / colsum[i]
// 512 thr, tile 32i x 32o, thread = 2i x 1o (o = lid&31, ip = lid>>5).
// Grid (8,16)=128 blocks. Warp: r broadcast (1 phase), tv coalesced (1 phase).
// Recips inline at staging (half the chip-wide MUFU vs o-tile-16).
// Colsum: 16x32 parallel partials (ascending-b segments), reduced once.
// ---------------------------------------------------------------------------
__global__ void __launch_bounds__(512)
k_relx(const float* __restrict__ x, const float* __restrict__ t) {
    __shared__ float Rs[128][32];   // [b][i_local] reciprocals
    __shared__ float Ts[128][32];   // [b][o_local]
    __shared__ float ps[16][32];    // colsum partials
    __shared__ float s_cs[32];

    const int i0  = blockIdx.x * 32;
    const int o0  = blockIdx.y * 32;
    const int lid = threadIdx.x;
    const int o   = lid & 31;      // o lane
    const int ip  = lid >> 5;      // i pair: 2ip, 2ip+1 (= warp id)

    // Parallel colsum partials: thread (seg, il) sums 16 consecutive b's
    {
        const int il  = lid & 31;
        const int seg = lid >> 5;
        float s = 0.0f;
        #pragma unroll
        for (int j = 0; j < 16; j++)
            s += x[(seg * 16 + j) * IN_ + i0 + il];
        ps[seg][il] = s;
    }

    float acc0 = 0.f, acc1 = 0.f;

    for (int bb = 0; bb < B_; bb += 128) {
        #pragma unroll
        for (int k = 0; k < 2; k++) {       // Rs: 4096 floats = 1024 float4
            int e   = lid + k * 512;        // 0..1023
            int row = e >> 3;
            int c4  = (e & 7) * 4;
            float4 xv = *(const float4*)&x[(bb + row) * IN_ + i0 + c4];
            float4 rv;
            rv.x = 1.0f / (xv.x + EPS_);
            rv.y = 1.0f / (xv.y + EPS_);
            rv.z = 1.0f / (xv.z + EPS_);
            rv.w = 1.0f / (xv.w + EPS_);
            *(float4*)&Rs[row][c4] = rv;
        }
        #pragma unroll
        for (int k = 0; k < 2; k++) {       // Ts: 4096 floats
            int e   = lid + k * 512;
            int row = e >> 3;
            int c4  = (e & 7) * 4;
            *(float4*)&Ts[row][c4] = *(const float4*)&t[(bb + row) * OUT_ + o0 + c4];
        }
        __syncthreads();

        if (bb == 0 && lid < 32) {          // reduce colsum partials once
            float s = ps[0][lid];
            #pragma unroll
            for (int c = 1; c < 16; c++) s += ps[c][lid];
            s_cs[lid] = s;
        }

        #pragma unroll 8
        for (int b = 0; b < 128; b++) {
            float2 r  = *(const float2*)&Rs[b][2 * ip];
            float  tv = Ts[b][o];
            acc0 += fminf(tv * r.x, 1.0f);
            acc1 += fminf(tv * r.y, 1.0f);
        }
        __syncthreads();
    }

    const int i_0 = i0 + 2 * ip, i_1 = i_0 + 1;
    const int oo  = o0 + o;
    g_relx[i_0 * OUT_ + oo] = acc0 / s_cs[2 * ip];
    g_relx[i_1 * OUT_ + oo] = acc1 / s_cs[2 * ip + 1];
}

// ---------------------------------------------------------------------------
// Kernel 2: R10 k_argmax verbatim (best-run bytes): w-argmax prologue +
// fmax-only inner loop, chunk-of-32 tracking, in-smem rescan (exact first
// max), direct outputs. Tile 16b x 32o, 256 thr, 1b x 2o/thread.
// Grid (16,16)=256 blocks.
// ---------------------------------------------------------------------------
__global__ void k_argmax(const float* __restrict__ x,
                         const float* __restrict__ w,
                         float* __restrict__ outx,
                         float* __restrict__ outw) {
    __shared__ float Xs[16][132];   // [b_local][i] half-tile (128 i + pad)
    __shared__ float Rl[128][32];   // [i][o_local]
    __shared__ float sv[8][32];
    __shared__ int   si[8][32];
    __shared__ float s_wv[32];
    __shared__ int   s_iw[32];

    const int b0  = blockIdx.x * 16;
    const int o0  = blockIdx.y * 32;
    const int lid = threadIdx.x;
    const int to  = lid & 15;    // o pair: 2to, 2to+1
    const int tb  = lid >> 4;    // b: 0..15

    // --- w-argmax for this block's 32 o's: thread (ic, ol) scans 32 i's ---
    {
        const int ol = lid & 31;
        const int ic = lid >> 5;
        const int o  = o0 + ol;
        float best = -1.f;
        int   bi   = 0;
        #pragma unroll
        for (int j = 0; j < 32; j++) {
            int i = ic * 32 + j;
            float v = w[i * OUT_ + o];
            if (v > best) { best = v; bi = i; }
        }
        sv[ic][ol] = best;
        si[ic][ol] = bi;
    }
    __syncthreads();
    if (lid < 32) {
        float bv = sv[0][lid];
        int   ix = si[0][lid];
        #pragma unroll
        for (int c = 1; c < 8; c++)
            if (sv[c][lid] > bv) { bv = sv[c][lid]; ix = si[c][lid]; }
        s_wv[lid] = bv;
        s_iw[lid] = ix;
    }

    // --- main argmax: 2 halves of 128 i ---
    float best0 = -1.f, best1 = -1.f;
    int   bc0 = 0, bc1 = 0;
    int   id0 = 0, id1 = 0;

    for (int half = 0; half < 2; half++) {
        const int iz = half * 128;
        #pragma unroll
        for (int k = 0; k < 2; k++) {       // Xs: [16 b][128 i], float4 rows
            int e   = lid + k * 256;
            int row = e >> 5;               // b-local 0..15
            int c4  = (e & 31) * 4;         // i-local 0..124
            *(float4*)&Xs[row][c4] = *(const float4*)&x[(b0 + row) * IN_ + iz + c4];
        }
        #pragma unroll
        for (int k = 0; k < 4; k++) {       // Rl: [128 i][32 o]
            int e   = lid + k * 256;
            int row = e >> 3;
            int c4  = (e & 7) * 4;
            *(float4*)&Rl[row][c4] = *(const float4*)&g_relx[(iz + row) * OUT_ + o0 + c4];
        }
        __syncthreads();

        #pragma unroll
        for (int c = 0; c < 4; c++) {
            float cm0 = -1.f, cm1 = -1.f;
            #pragma unroll
            for (int j = 0; j < 32; j++) {
                int i = c * 32 + j;
                float  xv = Xs[tb][i];
                float2 rv = *(const float2*)&Rl[i][2 * to];
                cm0 = fmaxf(cm0, xv * rv.x);
                cm1 = fmaxf(cm1, xv * rv.y);
            }
            const int cb = iz + c * 32;
            if (cm0 > best0) { best0 = cm0; bc0 = cb; }
            if (cm1 > best1) { best1 = cm1; bc1 = cb; }
        }

        // In-smem rescans (descending j, == overwrite -> exact first index)
        if (bc0 >= iz) {
            const int cl = bc0 - iz;
            #pragma unroll 8
            for (int j = 31; j >= 0; j--)
                if (Xs[tb][cl + j] * Rl[cl + j][2 * to] == best0) id0 = bc0 + j;
        }
        if (bc1 >= iz) {
            const int cl = bc1 - iz;
            #pragma unroll 8
            for (int j = 31; j >= 0; j--)
                if (Xs[tb][cl + j] * Rl[cl + j][2 * to + 1] == best1) id1 = bc1 + j;
        }
        __syncthreads();
    }

    const int b  = b0 + tb;
    const int o_ = o0 + 2 * to;

    float2 ox;
    ox.x = x[b * IN_ + id0] * w[id0 * OUT_ + o_];
    ox.y = x[b * IN_ + id1] * w[id1 * OUT_ + o_ + 1];
    *(float2*)&outx[b * OUT_ + o_] = ox;

    const int lo0 = 2 * to, lo1 = 2 * to + 1;
    float2 ow;
    ow.x = x[b * IN_ + s_iw[lo0]] * s_wv[lo0];
    ow.y = x[b * IN_ + s_iw[lo1]] * s_wv[lo1];
    *(float2*)&outw[b * OUT_ + o_] = ow;
}

// ---------------------------------------------------------------------------
extern "C" void kernel_launch(void* const* d_in, const int* in_sizes, int n_in,
                              void* d_out, int out_size) {
    const float* x = (const float*)d_in[0];
    const float* w = (const float*)d_in[1];
    const float* t = (const float*)d_in[2];
    float* outx = (float*)d_out;
    float* outw = (float*)d_out + B_ * OUT_;

    k_relx  <<<dim3(8, 16),  512>>>(x, t);
    k_argmax<<<dim3(16, 16), 256>>>(x, w, outx, outw);
}

// round 16
// speedup vs baseline: 1.2782x; 1.0904x over previous
#include <cuda_runtime.h>

#define B_   256
#define IN_  256
#define OUT_ 512
#define EPS_ 1e-7f

__device__ float g_relx[IN_ * OUT_];   // rel_x[i][o]
__device__ int   g_iw[OUT_];           // argmax_i w[i,o]
__device__ float g_wv[OUT_];           // w[iw,o]

// ---------------------------------------------------------------------------
// Kernel 1: grid (8,17), 512 thr.
//  y<16 : rel_x tiles (R15 verbatim): 32i x 32o, 2i x 1o/thread.
//  y==16: w-argmax role, 8 blocks, each 64 o's (8 i-chunks x 64 o-lanes,
//         exact first-max merge) -> g_iw/g_wv.
// ---------------------------------------------------------------------------
__global__ void __launch_bounds__(512)
k_relx(const float* __restrict__ x, const float* __restrict__ t,
       const float* __restrict__ w) {
    if (blockIdx.y == 16) {
        // ---- w-argmax role ----
        __shared__ float sv[8][64];
        __shared__ int   si[8][64];
        const int lid = threadIdx.x;
        const int ol  = lid & 63;            // o lane (64 per block)
        const int ic  = lid >> 6;            // i-chunk 0..7
        const int o   = blockIdx.x * 64 + ol;
        float best = -1.f;
        int   bi   = 0;
        #pragma unroll
        for (int j = 0; j < 32; j++) {
            int i = ic * 32 + j;
            float v = w[i * OUT_ + o];
            if (v > best) { best = v; bi = i; }
        }
        sv[ic][ol] = best;
        si[ic][ol] = bi;
        __syncthreads();
        if (lid < 64) {
            float bv = sv[0][lid];
            int   ix = si[0][lid];
            #pragma unroll
            for (int c = 1; c < 8; c++)
                if (sv[c][lid] > bv) { bv = sv[c][lid]; ix = si[c][lid]; }
            g_wv[blockIdx.x * 64 + lid] = bv;
            g_iw[blockIdx.x * 64 + lid] = ix;
        }
        return;
    }

    // ---- rel_x role (R15 verbatim) ----
    __shared__ float Rs[128][32];   // [b][i_local] reciprocals
    __shared__ float Ts[128][32];   // [b][o_local]
    __shared__ float ps[16][32];    // colsum partials
    __shared__ float s_cs[32];

    const int i0  = blockIdx.x * 32;
    const int o0  = blockIdx.y * 32;
    const int lid = threadIdx.x;
    const int o   = lid & 31;      // o lane
    const int ip  = lid >> 5;      // i pair: 2ip, 2ip+1

    {
        const int il  = lid & 31;
        const int seg = lid >> 5;
        float s = 0.0f;
        #pragma unroll
        for (int j = 0; j < 16; j++)
            s += x[(seg * 16 + j) * IN_ + i0 + il];
        ps[seg][il] = s;
    }

    float acc0 = 0.f, acc1 = 0.f;

    for (int bb = 0; bb < B_; bb += 128) {
        #pragma unroll
        for (int k = 0; k < 2; k++) {
            int e   = lid + k * 512;
            int row = e >> 3;
            int c4  = (e & 7) * 4;
            float4 xv = *(const float4*)&x[(bb + row) * IN_ + i0 + c4];
            float4 rv;
            rv.x = 1.0f / (xv.x + EPS_);
            rv.y = 1.0f / (xv.y + EPS_);
            rv.z = 1.0f / (xv.z + EPS_);
            rv.w = 1.0f / (xv.w + EPS_);
            *(float4*)&Rs[row][c4] = rv;
        }
        #pragma unroll
        for (int k = 0; k < 2; k++) {
            int e   = lid + k * 512;
            int row = e >> 3;
            int c4  = (e & 7) * 4;
            *(float4*)&Ts[row][c4] = *(const float4*)&t[(bb + row) * OUT_ + o0 + c4];
        }
        __syncthreads();

        if (bb == 0 && lid < 32) {
            float s = ps[0][lid];
            #pragma unroll
            for (int c = 1; c < 16; c++) s += ps[c][lid];
            s_cs[lid] = s;
        }

        #pragma unroll 8
        for (int b = 0; b < 128; b++) {
            float2 r  = *(const float2*)&Rs[b][2 * ip];
            float  tv = Ts[b][o];
            acc0 += fminf(tv * r.x, 1.0f);
            acc1 += fminf(tv * r.y, 1.0f);
        }
        __syncthreads();
    }

    const int i_0 = i0 + 2 * ip, i_1 = i_0 + 1;
    const int oo  = o0 + o;
    g_relx[i_0 * OUT_ + oo] = acc0 / s_cs[2 * ip];
    g_relx[i_1 * OUT_ + oo] = acc1 / s_cs[2 * ip + 1];
}

// ---------------------------------------------------------------------------
// Kernel 2: argmax, one thread per output. Grid (32,16)=512 blocks, 256 thr.
// Block = 8b x 32o, warp = 1b x 32o (b=warp id, o=lane). Full i-range in
// smem: Rl[i][lane] coalesced row reads, Xs[bl][i] broadcast float4.
// fmax-only + chunk-of-32 tracking + in-smem rescan (exact first-max).
// No cross-block combine; w-argmax read from g_iw/g_wv.
// ---------------------------------------------------------------------------
__global__ void k_argmax(const float* __restrict__ x,
                         const float* __restrict__ w,
                         float* __restrict__ outx,
                         float* __restrict__ outw) {
    __shared__ float Xs[8][260];    // [b_local][i] full i-range + pad
    __shared__ float Rl[256][32];   // [i][o_local]

    const int b0   = blockIdx.x * 8;
    const int o0   = blockIdx.y * 32;
    const int lid  = threadIdx.x;
    const int lane = lid & 31;      // o-local
    const int bl   = lid >> 5;      // b-local = warp id

    // --- stage Xs: 8 rows x 256 i = 512 float4 ---
    #pragma unroll
    for (int k = 0; k < 2; k++) {
        int e   = lid + k * 256;        // 0..511
        int row = e >> 6;               // 0..7
        int c4  = (e & 63) * 4;         // 0..252
        *(float4*)&Xs[row][c4] = *(const float4*)&x[(b0 + row) * IN_ + c4];
    }
    // --- stage Rl: 256 rows x 32 o = 2048 float4 ---
    #pragma unroll
    for (int k = 0; k < 8; k++) {
        int e   = lid + k * 256;        // 0..2047
        int row = e >> 3;               // 0..255
        int c4  = (e & 7) * 4;          // 0..28
        *(float4*)&Rl[row][c4] = *(const float4*)&g_relx[row * OUT_ + o0 + c4];
    }
    __syncthreads();

    // --- argmax over full i-range: fmax-only, chunk-of-32 tracking ---
    float best = -1.f;
    int   bc   = 0;

    #pragma unroll
    for (int c = 0; c < 8; c++) {
        float cm = -1.f;
        #pragma unroll
        for (int q = 0; q < 8; q++) {
            const int ib = c * 32 + q * 4;
            float4 xq = *(const float4*)&Xs[bl][ib];
            cm = fmaxf(cm, xq.x * Rl[ib + 0][lane]);
            cm = fmaxf(cm, xq.y * Rl[ib + 1][lane]);
            cm = fmaxf(cm, xq.z * Rl[ib + 2][lane]);
            cm = fmaxf(cm, xq.w * Rl[ib + 3][lane]);
        }
        if (cm > best) { best = cm; bc = c * 32; }
    }

    // --- in-smem rescan (descending j, == overwrite -> exact first index) ---
    int id = bc;
    #pragma unroll 8
    for (int j = 31; j >= 0; j--)
        if (Xs[bl][bc + j] * Rl[bc + j][lane] == best) id = bc + j;

    // --- outputs (coalesced over lane) ---
    const int b = b0 + bl;
    const int o = o0 + lane;

    outx[b * OUT_ + o] = x[b * IN_ + id] * w[id * OUT_ + o];
    outw[b * OUT_ + o] = x[b * IN_ + g_iw[o]] * g_wv[o];
}

// ---------------------------------------------------------------------------
extern "C" void kernel_launch(void* const* d_in, const int* in_sizes, int n_in,
                              void* d_out, int out_size) {
    const float* x = (const float*)d_in[0];
    const float* w = (const float*)d_in[1];
    const float* t = (const float*)d_in[2];
    float* outx = (float*)d_out;
    float* outw = (float*)d_out + B_ * OUT_;

    k_relx  <<<dim3(8, 17),  512>>>(x, t, w);
    k_argmax<<<dim3(32, 16), 256>>>(x, w, outx, outw);
}